// round 15
// baseline (speedup 1.0000x reference)
#include <cuda_runtime.h>
#include <cuda_bf16.h>
#include <cstdint>

#define NPTS 131072
#define GL 5
#define WD 256
#define OD 64
#define MTILE 64
#define NTHR 128

#define XSTR 528           /* x row stride bytes (512 data + 16 pad) */

/* weights in mma B-fragment order: [term][layer][kstep][ntile][lane] (uint2) */
__device__ __align__(1024) uint2 g_wfm[2][GL][16][32][32];  /* main: 1.31 MB */
__device__ __align__(1024) uint2 g_wfh[2][GL][16][8][32];   /* head: 328 KB  */

/* ---- shared memory byte offsets (per 64-row CTA) ---- */
#define SM_XHI 0                 /* 64 rows x 528B = 33792 */
#define SM_XLO 33792
#define SM_FFN 67584             /* 8 x 256 f32 */
#define SM_BH  75776             /* 5*bh: 256 f32 */
#define SM_BHH 76800             /* 5*bhh: 64 f32 */
#define SM_W0  77056             /* 3 x 256 f32 */
#define SM_B0  80128             /* 256 f32 */
#define SMEM_BYTES 81152

__device__ __forceinline__ uint32_t smem_u32(const void* p) {
    uint32_t a;
    asm("{ .reg .u64 t; cvta.to.shared.u64 t, %1; cvt.u32.u64 %0, t; }" : "=r"(a) : "l"(p));
    return a;
}

__device__ __forceinline__ void ldA(uint32_t* a, uint32_t addr) {
    asm volatile("ldmatrix.sync.aligned.m8n8.x4.shared.b16 {%0,%1,%2,%3}, [%4];"
        : "=r"(a[0]),"=r"(a[1]),"=r"(a[2]),"=r"(a[3]) : "r"(addr));
}
__device__ __forceinline__ void mma_bf16(float* c, const uint32_t* a, const uint32_t* b) {
    asm volatile("mma.sync.aligned.m16n8k16.row.col.f32.bf16.bf16.f32 "
        "{%0,%1,%2,%3},{%4,%5,%6,%7},{%8,%9},{%0,%1,%2,%3};"
        : "+f"(c[0]),"+f"(c[1]),"+f"(c[2]),"+f"(c[3])
        : "r"(a[0]),"r"(a[1]),"r"(a[2]),"r"(a[3]), "r"(b[0]),"r"(b[1]));
}

/* (v0,v1) -> bf16x2 hi word + bf16x2 residual word (unscaled) */
__device__ __forceinline__ void split2(float v0, float v1, uint32_t& hp, uint32_t& mp) {
    asm("cvt.rn.bf16x2.f32 %0, %1, %2;" : "=r"(hp) : "f"(v1), "f"(v0));
    float h0 = __uint_as_float(hp << 16);
    float h1 = __uint_as_float(hp & 0xffff0000u);
    asm("cvt.rn.bf16x2.f32 %0, %1, %2;" : "=r"(mp) : "f"(v1 - h1), "f"(v0 - h0));
}

__device__ __forceinline__ uint32_t bfpack(float v0, float v1, int term) {
    if (term == 1) {
        uint32_t r; asm("cvt.rn.bf16x2.f32 %0, %1, %2;" : "=r"(r) : "f"(v1), "f"(v0));
        return r;
    }
    __nv_bfloat16 h0 = __float2bfloat16(v0), h1 = __float2bfloat16(v1);
    float m0 = v0 - __bfloat162float(h0), m1 = v1 - __bfloat162float(h1);
    uint32_t r; asm("cvt.rn.bf16x2.f32 %0, %1, %2;" : "=r"(r) : "f"(m1), "f"(m0));
    return r;
}

/* ---------- prep: emit weights in mma B-fragment order ---------- */
__global__ void prep_kernel(const float* __restrict__ wh, const float* __restrict__ whh) {
    int idx = blockIdx.x * blockDim.x + threadIdx.x;
    const int MAIN_T = 2*GL*16*32*32;     /* 163840 */
    if (idx < MAIN_T) {
        int t = idx / (GL*16*32*32);
        int r = idx % (GL*16*32*32);
        int l = r / (16*32*32);
        int r2 = r % (16*32*32);
        int ks = r2 >> 10, gt = (r2 >> 5) & 31, lane = r2 & 31;
        int gid = lane >> 2, tig = lane & 3;
        int k0 = ks*16, n = gt*8 + gid;
        const float* W = wh + (long)l*WD*WD;
        float v00 = W[(k0 + 2*tig    )*WD + n];
        float v01 = W[(k0 + 2*tig + 1)*WD + n];
        float v10 = W[(k0 + 8 + 2*tig    )*WD + n];
        float v11 = W[(k0 + 8 + 2*tig + 1)*WD + n];
        g_wfm[t][l][ks][gt][lane] = make_uint2(bfpack(v00, v01, t), bfpack(v10, v11, t));
    } else {
        int j = idx - MAIN_T;
        if (j < 2*GL*16*8*32) {
            int t = j / (GL*16*8*32);
            int r = j % (GL*16*8*32);
            int l = r / (16*8*32);
            int r2 = r % (16*8*32);
            int ks = r2 >> 8, gt = (r2 >> 5) & 7, lane = r2 & 31;
            int gid = lane >> 2, tig = lane & 3;
            int k0 = ks*16, o = gt*8 + gid;
            const float* W = whh + (long)l*WD*OD;
            float v00 = W[(k0 + 2*tig    )*OD + o];
            float v01 = W[(k0 + 2*tig + 1)*OD + o];
            float v10 = W[(k0 + 8 + 2*tig    )*OD + o];
            float v11 = W[(k0 + 8 + 2*tig + 1)*OD + o];
            g_wfh[t][l][ks][gt][lane] = make_uint2(bfpack(v00, v01, t), bfpack(v10, v11, t));
        }
    }
}

/* ---------- main fused kernel: 128 thr, warp grid 2m x 2n, 3-term split,
              MTILE=64, 2 CTAs/SM, weights as LDG B-fragments ---------- */
__global__ void __launch_bounds__(NTHR, 2)
ffb_mma(const float* __restrict__ pos, const float* __restrict__ gf,
        const float* __restrict__ ffnA, const float* __restrict__ w0g,
        const float* __restrict__ b0g, const float* __restrict__ bhv,
        const float* __restrict__ bhhg, float* __restrict__ outp)
{
    extern __shared__ __align__(1024) unsigned char sm[];
    float* ffnS = (float*)(sm + SM_FFN);
    float* bhs  = (float*)(sm + SM_BH);
    float* bhhs = (float*)(sm + SM_BHH);
    float* w0s  = (float*)(sm + SM_W0);
    float* b0s  = (float*)(sm + SM_B0);
    const uint32_t smb = smem_u32(sm);

    const int tid = threadIdx.x, w = tid >> 5, lane = tid & 31;
    const int wm = w & 1, wn = w >> 1;       /* warp grid 2m x 2n */
    const int g = lane >> 2, qi = lane & 3;
    const long base = (long)blockIdx.x * MTILE;

    /* ldmatrix A lane geometry */
    const int atj = lane >> 3;
    const int a_row = (atj & 1)*8 + (lane & 7);
    const int a_cc  = atj >> 1;
    const int arow0 = 32*wm + a_row;
    const int arow1 = arow0 + 16;
    const uint32_t rbA0 = smb + (uint32_t)arow0*XSTR + (uint32_t)a_cc*16;
    const uint32_t rbA1 = smb + (uint32_t)arow1*XSTR + (uint32_t)a_cc*16;

    for (int i = tid; i < 768; i += NTHR) w0s[i] = w0g[i];
    for (int i = tid; i < 256; i += NTHR) b0s[i] = b0g[i];
    __syncthreads();   /* w0s/b0s staged before layer-0 reads */

    /* ---- layer 0: x = sin(5*(pos @ W0 + b0)) -> SMEM bf16 hi/mid ---- */
    {
        int r = tid >> 1, hh = tid & 1;      /* 128 thr: 64 rows x 2 col-halves */
        float p0 = pos[(base + r)*3], p1 = pos[(base + r)*3 + 1], p2 = pos[(base + r)*3 + 2];
        const uint32_t rb = (uint32_t)r*XSTR;
#pragma unroll
        for (int c = 0; c < 128; c += 2) {
            int c0 = hh*128 + c;
            float h0 = fmaf(p0, w0s[c0],   fmaf(p1, w0s[256+c0],   fmaf(p2, w0s[512+c0],   b0s[c0])));
            float h1 = fmaf(p0, w0s[c0+1], fmaf(p1, w0s[256+c0+1], fmaf(p2, w0s[512+c0+1], b0s[c0+1])));
            float v0 = __sinf(5.0f*h0), v1 = __sinf(5.0f*h1);
            uint32_t hp, mp; split2(v0, v1, hp, mp);
            uint32_t off = rb + (uint32_t)c0*2;
            *(uint32_t*)(sm + SM_XHI + off) = hp;
            *(uint32_t*)(sm + SM_XLO + off) = mp;
        }
    }
    __syncthreads();   /* layer-0 x visible to all warps' MMA */

    float oacc[2][4][4];
#pragma unroll
    for (int a = 0; a < 2; ++a)
#pragma unroll
        for (int b = 0; b < 4; ++b)
#pragma unroll
            for (int q = 0; q < 4; ++q) oacc[a][b][q] = 0.f;

    for (int l = 0; l < GL; ++l) {
        /* stage per-layer constants (epilogue reads; barrier below covers) */
        {
            float gsc = 6.283185307179586f * (float)(1 << l);
            for (int i = tid; i < 2048; i += NTHR) ffnS[i] = ffnA[l*2048 + i] * gsc;
            for (int i = tid; i < 256;  i += NTHR) bhs[i]  = 5.0f * bhv[l*256 + i];
            for (int i = tid; i < 64;   i += NTHR) bhhs[i] = 5.0f * bhhg[l*64 + i];
        }

        float acc[2][16][4];
#pragma unroll
        for (int mt = 0; mt < 2; ++mt)
#pragma unroll
            for (int nt = 0; nt < 16; ++nt)
#pragma unroll
                for (int q = 0; q < 4; ++q) acc[mt][nt][q] = 0.f;

        /* ---- main GEMM (3-term): t0 = Wm x Ah; t1 = Wh x (Ah+Am); no barriers ---- */
#pragma unroll
        for (int t = 0; t < 2; ++t) {
            const uint2* __restrict__ wp = &g_wfm[t][l][0][0][0];
            for (int ks = 0; ks < 16; ++ks) {
                const uint32_t koff = (uint32_t)ks*32;
                uint32_t ah0[4], ah1[4], am0[4], am1[4];
                ldA(ah0, rbA0 + SM_XHI + koff);
                ldA(ah1, rbA1 + SM_XHI + koff);
                if (t == 1) {
                    ldA(am0, rbA0 + SM_XLO + koff);
                    ldA(am1, rbA1 + SM_XLO + koff);
                }
                const uint2* __restrict__ wrow = wp + (ks*32 + wn*16)*32 + lane;
#pragma unroll
                for (int half = 0; half < 2; ++half) {
                    uint2 bv[8];
#pragma unroll
                    for (int j = 0; j < 8; ++j) bv[j] = wrow[(half*8 + j)*32];
#pragma unroll
                    for (int j = 0; j < 8; ++j) {
                        const int nt = half*8 + j;
                        uint32_t bb[2] = {bv[j].x, bv[j].y};
                        mma_bf16(acc[0][nt], ah0, bb);
                        mma_bf16(acc[1][nt], ah1, bb);
                        if (t == 1) {
                            mma_bf16(acc[0][nt], am0, bb);
                            mma_bf16(acc[1][nt], am1, bb);
                        }
                    }
                }
            }
        }
        __syncthreads();   /* all x reads + const staging done before epilogue writes */

        /* ---- epilogue: x_new = sin(5*D + 5*bh) + sin(gf @ ffnS) ---- */
#pragma unroll
        for (int mt = 0; mt < 2; ++mt) {
            const int r0 = 32*wm + 16*mt + g;
            float gfa[2][8];
#pragma unroll
            for (int p = 0; p < 2; ++p) {
                const float* gp = gf + (base + r0 + 8*p)*40 + l*8;
                float4 u = *(const float4*)gp, v2 = *(const float4*)(gp + 4);
                gfa[p][0]=u.x; gfa[p][1]=u.y; gfa[p][2]=u.z; gfa[p][3]=u.w;
                gfa[p][4]=v2.x; gfa[p][5]=v2.y; gfa[p][6]=v2.z; gfa[p][7]=v2.w;
            }
#pragma unroll
            for (int nt = 0; nt < 16; ++nt) {
                const int n0 = 128*wn + 8*nt + 2*qi;
                float rs00=0.f, rs01=0.f, rs10=0.f, rs11=0.f;
#pragma unroll
                for (int f = 0; f < 8; ++f) {
                    float2 fp = *(const float2*)&ffnS[f*256 + n0];
                    rs00 = fmaf(gfa[0][f], fp.x, rs00);
                    rs01 = fmaf(gfa[0][f], fp.y, rs01);
                    rs10 = fmaf(gfa[1][f], fp.x, rs10);
                    rs11 = fmaf(gfa[1][f], fp.y, rs11);
                }
                const float bh0 = bhs[n0], bh1 = bhs[n0+1];
                float v00 = __sinf(fmaf(acc[mt][nt][0], 5.0f, bh0)) + __sinf(rs00);
                float v01 = __sinf(fmaf(acc[mt][nt][1], 5.0f, bh1)) + __sinf(rs01);
                float v10 = __sinf(fmaf(acc[mt][nt][2], 5.0f, bh0)) + __sinf(rs10);
                float v11 = __sinf(fmaf(acc[mt][nt][3], 5.0f, bh1)) + __sinf(rs11);
                uint32_t hp, mp;
                split2(v00, v01, hp, mp);
                uint32_t off = (uint32_t)r0*XSTR + (uint32_t)n0*2;
                *(uint32_t*)(sm + SM_XHI + off) = hp;
                *(uint32_t*)(sm + SM_XLO + off) = mp;
                split2(v10, v11, hp, mp);
                off = (uint32_t)(r0+8)*XSTR + (uint32_t)n0*2;
                *(uint32_t*)(sm + SM_XHI + off) = hp;
                *(uint32_t*)(sm + SM_XLO + off) = mp;
            }
        }
        __syncthreads();   /* x_new visible before head MMA reads */

        /* ---- head GEMM (3-term): t0 = Hm x Ah; t1 = Hh x (Ah+Am) ---- */
        float acc2[2][4][4];
#pragma unroll
        for (int mt = 0; mt < 2; ++mt)
#pragma unroll
            for (int nt = 0; nt < 4; ++nt)
#pragma unroll
                for (int q = 0; q < 4; ++q) acc2[mt][nt][q] = 0.f;

#pragma unroll
        for (int t = 0; t < 2; ++t) {
            const uint2* __restrict__ wp = &g_wfh[t][l][0][0][0];
            for (int ks = 0; ks < 16; ++ks) {
                const uint32_t koff = (uint32_t)ks*32;
                uint32_t ah0[4], ah1[4], am0[4], am1[4];
                ldA(ah0, rbA0 + SM_XHI + koff);
                ldA(ah1, rbA1 + SM_XHI + koff);
                if (t == 1) {
                    ldA(am0, rbA0 + SM_XLO + koff);
                    ldA(am1, rbA1 + SM_XLO + koff);
                }
                const uint2* __restrict__ wrow = wp + (ks*8 + wn*4)*32 + lane;
                uint2 bv[4];
#pragma unroll
                for (int j = 0; j < 4; ++j) bv[j] = wrow[j*32];
#pragma unroll
                for (int j = 0; j < 4; ++j) {
                    uint32_t bb[2] = {bv[j].x, bv[j].y};
                    mma_bf16(acc2[0][j], ah0, bb);
                    mma_bf16(acc2[1][j], ah1, bb);
                    if (t == 1) {
                        mma_bf16(acc2[0][j], am0, bb);
                        mma_bf16(acc2[1][j], am1, bb);
                    }
                }
            }
        }

        /* ---- head epilogue: out += sin(5*D2 + 5*bhh) (registers only) ---- */
#pragma unroll
        for (int mt = 0; mt < 2; ++mt)
#pragma unroll
            for (int nt = 0; nt < 4; ++nt) {
                const int n0 = 32*wn + 8*nt + 2*qi;
                const float bh0 = bhhs[n0], bh1 = bhhs[n0+1];
                oacc[mt][nt][0] += __sinf(fmaf(acc2[mt][nt][0], 5.0f, bh0));
                oacc[mt][nt][1] += __sinf(fmaf(acc2[mt][nt][1], 5.0f, bh1));
                oacc[mt][nt][2] += __sinf(fmaf(acc2[mt][nt][2], 5.0f, bh0));
                oacc[mt][nt][3] += __sinf(fmaf(acc2[mt][nt][3], 5.0f, bh1));
            }
    }

    /* ---- output ---- */
#pragma unroll
    for (int mt = 0; mt < 2; ++mt)
#pragma unroll
        for (int p = 0; p < 2; ++p) {
            const long row = base + 32*wm + 16*mt + g + 8*p;
#pragma unroll
            for (int nt = 0; nt < 4; ++nt) {
                const int n0 = 32*wn + 8*nt + 2*qi;
                float2 v;
                v.x = oacc[mt][nt][2*p];
                v.y = oacc[mt][nt][2*p + 1];
                *(float2*)(outp + row*(long)OD + n0) = v;
            }
        }
}

extern "C" void kernel_launch(void* const* d_in, const int* in_sizes, int n_in,
                              void* d_out, int out_size) {
    const float *pos=0,*gfp=0,*ffn=0,*w0=0,*b0=0,*wh=0,*bh=0,*whh=0,*bhh=0;
    for (int i = 0; i < n_in; ++i) {
        const float* p = (const float*)d_in[i];
        switch (in_sizes[i]) {
            case NPTS*3:      pos = p; break;
            case NPTS*GL*8:   gfp = p; break;
            case GL*8*WD:     ffn = p; break;
            case 3*WD:        w0  = p; break;
            case WD:          b0  = p; break;
            case GL*WD*WD:    wh  = p; break;
            case GL*WD:       bh  = p; break;
            case GL*WD*OD:    whh = p; break;
            case GL*OD:       bhh = p; break;
        }
    }
    prep_kernel<<<800, 256>>>(wh, whh);
    cudaFuncSetAttribute(ffb_mma, cudaFuncAttributeMaxDynamicSharedMemorySize, SMEM_BYTES);
    ffb_mma<<<NPTS/MTILE, NTHR, SMEM_BYTES>>>(pos, gfp, ffn, w0, b0, bh, bhh, (float*)d_out);
}